// round 15
// baseline (speedup 1.0000x reference)
#include <cuda_runtime.h>
#include <math.h>

#define B1N 48
#define B2N 48
#define RN 36
#define LN 30
#define DN 1024
#define HN 4
#define ECH 64
#define NCHUNK (DN / ECH)
#define ISD 0.03125f
#define EPSV 1e-8f

// Scratch (device globals; no allocation in kernel_launch)
__device__ float g_k1[B1N * RN * DN];            // 1728 x 1024
__device__ float g_k2[B2N * LN * DN];            // 1440 x 1024
__device__ float g_Za[B2N * LN * DN];            // 1440 x 1024  (v2 @ w1a^T)
__device__ float g_Zb[B1N * RN * DN];            // 1728 x 1024  (v1 @ w1b^T)
__device__ float g_C[(B1N * RN) * (B2N * LN)];   // 1728 x 1440  (k1 . k2)

// ---------------------------------------------------------------------------
// f32x2 packed FMA + cp.async helpers
// ---------------------------------------------------------------------------
typedef unsigned long long u64;

__device__ __forceinline__ u64 fma2(u64 a, u64 b, u64 c) {
    u64 d;
    asm("fma.rn.f32x2 %0, %1, %2, %3;" : "=l"(d) : "l"(a), "l"(b), "l"(c));
    return d;
}
__device__ __forceinline__ u64 dup2(float p) {
    u64 d;
    asm("mov.b64 %0, {%1, %1};" : "=l"(d) : "f"(p));
    return d;
}
__device__ __forceinline__ float2 unpack2(u64 v) {
    return *reinterpret_cast<float2*>(&v);
}

__device__ __forceinline__ unsigned s2u(const void* p) {
    return (unsigned)__cvta_generic_to_shared(p);
}
__device__ __forceinline__ void cp16(unsigned dst, const float* src) {
    asm volatile("cp.async.cg.shared.global [%0], [%1], 16;" ::"r"(dst),
                 "l"(src));
}
__device__ __forceinline__ void cp16z(unsigned dst, const float* src, int ok) {
    int sz = ok ? 16 : 0;
    asm volatile("cp.async.cg.shared.global [%0], [%1], 16, %2;" ::"r"(dst),
                 "l"(src), "r"(sz));
}
__device__ __forceinline__ void cp_commit() {
    asm volatile("cp.async.commit_group;");
}
__device__ __forceinline__ void cp_wait1() {
    asm volatile("cp.async.wait_group 1;");
}
__device__ __forceinline__ void cp_wait0() {
    asm volatile("cp.async.wait_group 0;");
}

// ---------------------------------------------------------------------------
// NT GEMM core: BM=96, BN=64, 128 thr, 6x8 f32x2 microtile, GBK=32.
// Rows padded to 36 floats (conflict-free for both operands).
// Operand loads are LDS.128 (2 k-pairs per step) to cut issue count.
// ---------------------------------------------------------------------------
#define GBM 96
#define GBN 64
#define GBK 32
#define GNT (DN / GBK)

template <bool GUARD>
__device__ __forceinline__ void gemm_core(const float* __restrict__ A,
                                          const float* __restrict__ B,
                                          float* __restrict__ C, int N, int m0,
                                          int n0) {
    __shared__ __align__(16) float As[2][GBM][36];
    __shared__ __align__(16) float Bs[2][GBN][36];

    const int tid = threadIdx.x;
    const int tx = tid & 7;
    const int ty = tid >> 3;

    u64 acc[6][8];
#pragma unroll
    for (int i = 0; i < 6; i++)
#pragma unroll
        for (int j = 0; j < 8; j++) acc[i][j] = 0ull;

    {
#pragma unroll
        for (int i = 0; i < 6; i++) {
            int idx = tid + i * 128;
            int r = idx >> 3, kq = idx & 7;
            cp16(s2u(&As[0][r][kq * 4]), A + (size_t)(m0 + r) * DN + kq * 4);
        }
#pragma unroll
        for (int i = 0; i < 4; i++) {
            int idx = tid + i * 128;
            int r = idx >> 3, kq = idx & 7;
            const float* src = B + (size_t)(n0 + r) * DN + kq * 4;
            if (GUARD)
                cp16z(s2u(&Bs[0][r][kq * 4]), src, n0 + r < N);
            else
                cp16(s2u(&Bs[0][r][kq * 4]), src);
        }
        cp_commit();
    }

    for (int kt = 0; kt < GNT; kt++) {
        const int buf = kt & 1;
        if (kt + 1 < GNT) {
            const int k0 = (kt + 1) * GBK;
            const int nb = buf ^ 1;
#pragma unroll
            for (int i = 0; i < 6; i++) {
                int idx = tid + i * 128;
                int r = idx >> 3, kq = idx & 7;
                cp16(s2u(&As[nb][r][kq * 4]),
                     A + (size_t)(m0 + r) * DN + k0 + kq * 4);
            }
#pragma unroll
            for (int i = 0; i < 4; i++) {
                int idx = tid + i * 128;
                int r = idx >> 3, kq = idx & 7;
                const float* src = B + (size_t)(n0 + r) * DN + k0 + kq * 4;
                if (GUARD)
                    cp16z(s2u(&Bs[nb][r][kq * 4]), src, n0 + r < N);
                else
                    cp16(s2u(&Bs[nb][r][kq * 4]), src);
            }
            cp_commit();
            cp_wait1();
        } else {
            cp_wait0();
        }
        __syncthreads();

#pragma unroll
        for (int p = 0; p < 8; p++) {   // 8 double-steps x 2 k-pairs
            u64 av[6][2], bv[8][2];
#pragma unroll
            for (int i = 0; i < 6; i++) {
                float4 t =
                    *reinterpret_cast<const float4*>(&As[buf][ty * 6 + i][4 * p]);
                av[i][0] = *reinterpret_cast<u64*>(&t.x);
                av[i][1] = *reinterpret_cast<u64*>(&t.z);
            }
#pragma unroll
            for (int j = 0; j < 8; j++) {
                float4 t =
                    *reinterpret_cast<const float4*>(&Bs[buf][j * 8 + tx][4 * p]);
                bv[j][0] = *reinterpret_cast<u64*>(&t.x);
                bv[j][1] = *reinterpret_cast<u64*>(&t.z);
            }
#pragma unroll
            for (int i = 0; i < 6; i++)
#pragma unroll
                for (int j = 0; j < 8; j++) {
                    acc[i][j] = fma2(av[i][0], bv[j][0], acc[i][j]);
                    acc[i][j] = fma2(av[i][1], bv[j][1], acc[i][j]);
                }
        }
        __syncthreads();
    }

#pragma unroll
    for (int i = 0; i < 6; i++) {
        const int m = m0 + ty * 6 + i;
#pragma unroll
        for (int j = 0; j < 8; j++) {
            const int n = n0 + tx + j * 8;
            float2 v = *reinterpret_cast<float2*>(&acc[i][j]);
            if (!GUARD || n < N) C[(size_t)m * N + n] = v.x + v.y;
        }
    }
}

__global__ __launch_bounds__(128) void gemm_proj(
    const float* __restrict__ v1, const float* __restrict__ v2,
    const float* __restrict__ w_img, const float* __restrict__ w_txt,
    const float* __restrict__ w1a, const float* __restrict__ w1b,
    float* __restrict__ k1, float* __restrict__ k2, float* __restrict__ Za,
    float* __restrict__ Zb) {
    const float* A;
    const float* B;
    float* C;
    int M;
    switch (blockIdx.z) {
        case 0: A = v1; B = w_img; C = k1; M = B1N * RN; break;
        case 1: A = v1; B = w1b; C = Zb; M = B1N * RN; break;
        case 2: A = v2; B = w_txt; C = k2; M = B2N * LN; break;
        default: A = v2; B = w1a; C = Za; M = B2N * LN; break;
    }
    const int m0 = blockIdx.y * GBM;
    if (m0 >= M) return;
    gemm_core<false>(A, B, C, DN, m0, blockIdx.x * GBN);
}

__global__ __launch_bounds__(128) void gemm_cmat(const float* __restrict__ k1,
                                                 const float* __restrict__ k2,
                                                 float* __restrict__ C) {
    gemm_core<true>(k1, k2, C, B2N * LN, blockIdx.y * GBM, blockIdx.x * GBN);
}

// ---------------------------------------------------------------------------
// Fused per-(a,b)-pair kernel — R11 shape (160 thr, 8 e-lanes, ECH=64,
// double-buffered cp.async, LDS.128 z loads) + packed LDS.64 p-loads
// (l and r stepped by 2).
// ---------------------------------------------------------------------------
#define FTH 160
#define FNW (FTH / 32)
#define EQ4 (ECH / 4)

__global__ __launch_bounds__(FTH) void fused_pair(
    const float* __restrict__ v1, const float* __restrict__ v2,
    const float* __restrict__ Cbig, const float* __restrict__ Za,
    const float* __restrict__ Zb, const float* __restrict__ w2a,
    const float* __restrict__ b1a, const float* __restrict__ w2b,
    const float* __restrict__ b1b, float* __restrict__ out) {
    const int b = blockIdx.x;
    const int a = blockIdx.y;
    const int tid = threadIdx.x;
    const int lane = tid & 31;
    const int warp = tid >> 5;

    __shared__ __align__(16) float ZacS[2][LN * ECH];
    __shared__ __align__(16) float ZbcS[2][RN * ECH];
    __shared__ __align__(16) float w2acS[2][HN * ECH];
    __shared__ __align__(16) float w2bcS[2][HN * ECH];
    __shared__ __align__(16) float b1acS[2][ECH];
    __shared__ __align__(16) float b1bcS[2][ECH];
    __shared__ __align__(16) float p2s[RN][LN];   // softmax over l
    __shared__ __align__(16) float p1s[LN][RN];   // softmax over r
    __shared__ float sa[RN][HN];
    __shared__ float sb[LN][HN];

    float* Csp = ZbcS[1];
    float* pa_ = ZbcS[0];
    float* pb_ = pa_ + HN * RN;
    float* tr_ = pb_ + HN * LN;
    float* tl_ = tr_ + RN;
    float* qa_ = tl_ + LN;
    float* qb_ = qa_ + LN;
    float* red_ = qb_ + RN;

    const float* ZaB = Za + (size_t)b * LN * DN;
    const float* ZbA = Zb + (size_t)a * RN * DN;

    auto stage = [&](int c, int sb_) {
        const int e0c = c * ECH;
        for (int p = tid; p < LN * EQ4; p += FTH) {
            int l = p >> 4, q = p & 15;
            cp16(s2u(&ZacS[sb_][l * ECH + q * 4]),
                 ZaB + (size_t)l * DN + e0c + q * 4);
        }
        for (int p = tid; p < RN * EQ4; p += FTH) {
            int r = p >> 4, q = p & 15;
            cp16(s2u(&ZbcS[sb_][r * ECH + q * 4]),
                 ZbA + (size_t)r * DN + e0c + q * 4);
        }
        for (int p = tid; p < HN * EQ4; p += FTH) {
            int h = p >> 4, q = p & 15;
            cp16(s2u(&w2acS[sb_][h * ECH + q * 4]), w2a + h * DN + e0c + q * 4);
            cp16(s2u(&w2bcS[sb_][h * ECH + q * 4]), w2b + h * DN + e0c + q * 4);
        }
        if (tid < EQ4)
            cp16(s2u(&b1acS[sb_][tid * 4]), b1a + e0c + tid * 4);
        else if (tid < 2 * EQ4)
            cp16(s2u(&b1bcS[sb_][(tid - EQ4) * 4]), b1b + e0c + (tid - EQ4) * 4);
    };

    stage(0, 0);
    cp_commit();

    for (int p = tid; p < RN * LN; p += FTH) {
        int r = p / LN, l = p % LN;
        Csp[p] = Cbig[(size_t)(a * RN + r) * (B2N * LN) + b * LN + l] * ISD;
    }
    __syncthreads();

    for (int r = warp; r < RN; r += FNW) {
        float x = (lane < LN) ? Csp[r * LN + lane] : -1e30f;
        float m = x;
#pragma unroll
        for (int o = 16; o; o >>= 1) m = fmaxf(m, __shfl_xor_sync(~0u, m, o));
        float e = (lane < LN) ? __expf(x - m) : 0.f;
        float s = e;
#pragma unroll
        for (int o = 16; o; o >>= 1) s += __shfl_xor_sync(~0u, s, o);
        if (lane < LN) p2s[r][lane] = e / s;
    }
    for (int l = warp; l < LN; l += FNW) {
        float x0 = Csp[lane * LN + l];
        float x1 = (lane < RN - 32) ? Csp[(lane + 32) * LN + l] : -1e30f;
        float m = fmaxf(x0, x1);
#pragma unroll
        for (int o = 16; o; o >>= 1) m = fmaxf(m, __shfl_xor_sync(~0u, m, o));
        float e0 = __expf(x0 - m);
        float e1 = (lane < RN - 32) ? __expf(x1 - m) : 0.f;
        float s = e0 + e1;
#pragma unroll
        for (int o = 16; o; o >>= 1) s += __shfl_xor_sync(~0u, s, o);
        p1s[l][lane] = e0 / s;
        if (lane < RN - 32) p1s[l][lane + 32] = e1 / s;
    }
    __syncthreads();

    const int isH1 = (tid < 72);
    const int isH2 = (tid >= 72 && tid < 152);
    const int rg = tid >> 3;
    const int lg = (tid - 72) >> 3;
    const int el = (isH1 ? tid : tid - 72) & 7;
    const int r0 = rg * 4;
    const int l0 = lg * 3;
    const int eb = el * 4;

    float saacc[4][4];
    float sbacc[3][4];
#pragma unroll
    for (int i = 0; i < 4; i++)
#pragma unroll
        for (int h = 0; h < 4; h++) saacc[i][h] = 0.f;
#pragma unroll
    for (int i = 0; i < 3; i++)
#pragma unroll
        for (int h = 0; h < 4; h++) sbacc[i][h] = 0.f;

    for (int c = 0; c < NCHUNK; c++) {
        const int buf = c & 1;
        if (c + 1 < NCHUNK) {
            stage(c + 1, buf ^ 1);
            cp_commit();
            cp_wait1();
        } else {
            cp_wait0();
        }
        __syncthreads();

        if (isH1) {
            u64 tmp[4][4];
#pragma unroll
            for (int i = 0; i < 4; i++)
#pragma unroll
                for (int k = 0; k < 4; k++) tmp[i][k] = 0ull;
            // l stepped by 2; p pairs loaded as LDS.64 (rows 120B, l even ok)
            for (int l = 0; l < LN; l += 2) {
                float4 za0 = *reinterpret_cast<const float4*>(
                    &ZacS[buf][l * ECH + eb]);
                float4 za1 = *reinterpret_cast<const float4*>(
                    &ZacS[buf][l * ECH + eb + 32]);
                float4 zb0 = *reinterpret_cast<const float4*>(
                    &ZacS[buf][(l + 1) * ECH + eb]);
                float4 zb1 = *reinterpret_cast<const float4*>(
                    &ZacS[buf][(l + 1) * ECH + eb + 32]);
                u64 zA[4], zB[4];
                zA[0] = *reinterpret_cast<u64*>(&za0.x);
                zA[1] = *reinterpret_cast<u64*>(&za0.z);
                zA[2] = *reinterpret_cast<u64*>(&za1.x);
                zA[3] = *reinterpret_cast<u64*>(&za1.z);
                zB[0] = *reinterpret_cast<u64*>(&zb0.x);
                zB[1] = *reinterpret_cast<u64*>(&zb0.z);
                zB[2] = *reinterpret_cast<u64*>(&zb1.x);
                zB[3] = *reinterpret_cast<u64*>(&zb1.z);
#pragma unroll
                for (int i = 0; i < 4; i++) {
                    u64 pp = *reinterpret_cast<const u64*>(&p2s[r0 + i][l]);
                    float2 pv = unpack2(pp);
                    u64 pd0 = dup2(pv.x);
                    u64 pd1 = dup2(pv.y);
#pragma unroll
                    for (int k = 0; k < 4; k++) {
                        tmp[i][k] = fma2(pd0, zA[k], tmp[i][k]);
                        tmp[i][k] = fma2(pd1, zB[k], tmp[i][k]);
                    }
                }
            }
#pragma unroll
            for (int k = 0; k < 4; k++) {
                const int e = eb + (k & 1) * 2 + (k >> 1) * 32;
                float bb0 = b1acS[buf][e], bb1 = b1acS[buf][e + 1];
                float w0[4], w1[4];
#pragma unroll
                for (int h = 0; h < 4; h++) {
                    w0[h] = w2acS[buf][h * ECH + e];
                    w1[h] = w2acS[buf][h * ECH + e + 1];
                }
#pragma unroll
                for (int i = 0; i < 4; i++) {
                    float2 t = unpack2(tmp[i][k]);
                    float h0 = fmaxf(t.x + bb0, 0.f);
                    float h1 = fmaxf(t.y + bb1, 0.f);
#pragma unroll
                    for (int h = 0; h < 4; h++)
                        saacc[i][h] += w0[h] * h0 + w1[h] * h1;
                }
            }
        } else if (isH2) {
            u64 tmp[3][4];
#pragma unroll
            for (int i = 0; i < 3; i++)
#pragma unroll
                for (int k = 0; k < 4; k++) tmp[i][k] = 0ull;
            // r stepped by 2; p pairs loaded as LDS.64 (rows 144B, r even ok)
            for (int r = 0; r < RN; r += 2) {
                float4 za0 = *reinterpret_cast<const float4*>(
                    &ZbcS[buf][r * ECH + eb]);
                float4 za1 = *reinterpret_cast<const float4*>(
                    &ZbcS[buf][r * ECH + eb + 32]);
                float4 zb0 = *reinterpret_cast<const float4*>(
                    &ZbcS[buf][(r + 1) * ECH + eb]);
                float4 zb1 = *reinterpret_cast<const float4*>(
                    &ZbcS[buf][(r + 1) * ECH + eb + 32]);
                u64 zA[4], zB[4];
                zA[0] = *reinterpret_cast<u64*>(&za0.x);
                zA[1] = *reinterpret_cast<u64*>(&za0.z);
                zA[2] = *reinterpret_cast<u64*>(&za1.x);
                zA[3] = *reinterpret_cast<u64*>(&za1.z);
                zB[0] = *reinterpret_cast<u64*>(&zb0.x);
                zB[1] = *reinterpret_cast<u64*>(&zb0.z);
                zB[2] = *reinterpret_cast<u64*>(&zb1.x);
                zB[3] = *reinterpret_cast<u64*>(&zb1.z);
#pragma unroll
                for (int i = 0; i < 3; i++) {
                    u64 pp = *reinterpret_cast<const u64*>(&p1s[l0 + i][r]);
                    float2 pv = unpack2(pp);
                    u64 pd0 = dup2(pv.x);
                    u64 pd1 = dup2(pv.y);
#pragma unroll
                    for (int k = 0; k < 4; k++) {
                        tmp[i][k] = fma2(pd0, zA[k], tmp[i][k]);
                        tmp[i][k] = fma2(pd1, zB[k], tmp[i][k]);
                    }
                }
            }
#pragma unroll
            for (int k = 0; k < 4; k++) {
                const int e = eb + (k & 1) * 2 + (k >> 1) * 32;
                float bb0 = b1bcS[buf][e], bb1 = b1bcS[buf][e + 1];
                float w0[4], w1[4];
#pragma unroll
                for (int h = 0; h < 4; h++) {
                    w0[h] = w2bcS[buf][h * ECH + e];
                    w1[h] = w2bcS[buf][h * ECH + e + 1];
                }
#pragma unroll
                for (int i = 0; i < 3; i++) {
                    float2 t = unpack2(tmp[i][k]);
                    float h0 = fmaxf(t.x + bb0, 0.f);
                    float h1 = fmaxf(t.y + bb1, 0.f);
#pragma unroll
                    for (int h = 0; h < 4; h++)
                        sbacc[i][h] += w0[h] * h0 + w1[h] * h1;
                }
            }
        }
        __syncthreads();
    }

    {
        const unsigned gm = 0xFFu << (lane & 24);
        if (isH1) {
#pragma unroll
            for (int off = 4; off; off >>= 1)
#pragma unroll
                for (int i = 0; i < 4; i++)
#pragma unroll
                    for (int h = 0; h < 4; h++)
                        saacc[i][h] += __shfl_xor_sync(gm, saacc[i][h], off);
            if (el == 0)
#pragma unroll
                for (int i = 0; i < 4; i++)
#pragma unroll
                    for (int h = 0; h < 4; h++) sa[r0 + i][h] = saacc[i][h];
        } else if (isH2) {
#pragma unroll
            for (int off = 4; off; off >>= 1)
#pragma unroll
                for (int i = 0; i < 3; i++)
#pragma unroll
                    for (int h = 0; h < 4; h++)
                        sbacc[i][h] += __shfl_xor_sync(gm, sbacc[i][h], off);
            if (el == 0)
#pragma unroll
                for (int i = 0; i < 3; i++)
#pragma unroll
                    for (int h = 0; h < 4; h++) sb[l0 + i][h] = sbacc[i][h];
        }
    }
    __syncthreads();

    if (tid < HN) {
        int h = tid;
        float m = -1e30f;
        for (int r = 0; r < RN; r++) m = fmaxf(m, sa[r][h]);
        float s = 0.f;
        for (int r = 0; r < RN; r++) {
            float e = __expf(sa[r][h] - m);
            pa_[h * RN + r] = e;
            s += e;
        }
        float inv = 1.f / s;
        for (int r = 0; r < RN; r++) pa_[h * RN + r] *= inv;
    } else if (tid < 2 * HN) {
        int h = tid - HN;
        float m = -1e30f;
        for (int l = 0; l < LN; l++) m = fmaxf(m, sb[l][h]);
        float s = 0.f;
        for (int l = 0; l < LN; l++) {
            float e = __expf(sb[l][h] - m);
            pb_[h * LN + l] = e;
            s += e;
        }
        float inv = 1.f / s;
        for (int l = 0; l < LN; l++) pb_[h * LN + l] *= inv;
    }
    __syncthreads();

    if (tid < RN) {
        float s = 0.f;
        for (int h = 0; h < HN; h++) s += pa_[h * RN + tid];
        tr_[tid] = s;
    } else if (tid >= 64 && tid < 64 + LN) {
        int l = tid - 64;
        float s = 0.f;
        for (int h = 0; h < HN; h++) s += pb_[h * LN + l];
        tl_[l] = s;
    }
    __syncthreads();
    if (tid < LN) {
        float s = 0.f;
        for (int r = 0; r < RN; r++) s += tr_[r] * p2s[r][tid];
        qa_[tid] = 0.25f * s;
    } else if (tid >= 64 && tid < 64 + RN) {
        int r = tid - 64;
        float s = 0.f;
        for (int l = 0; l < LN; l++) s += tl_[l] * p1s[l][r];
        qb_[r] = 0.25f * s;
    }
    __syncthreads();

    float n11 = 0.f, n12 = 0.f, n22 = 0.f;
    const float* v2b = v2 + (size_t)b * LN * DN;
    const float* v1a = v1 + (size_t)a * RN * DN;
    for (int d = tid; d < DN; d += FTH) {
        float u1 = 0.f;
#pragma unroll
        for (int l = 0; l < LN; l++) u1 += qa_[l] * v2b[(size_t)l * DN + d];
        float u2 = 0.f;
#pragma unroll
        for (int r = 0; r < RN; r++) u2 += qb_[r] * v1a[(size_t)r * DN + d];
        n11 += u1 * u1;
        n12 += u1 * u2;
        n22 += u2 * u2;
    }
#pragma unroll
    for (int o = 16; o; o >>= 1) {
        n11 += __shfl_xor_sync(~0u, n11, o);
        n12 += __shfl_xor_sync(~0u, n12, o);
        n22 += __shfl_xor_sync(~0u, n22, o);
    }
    if (lane == 0) {
        red_[0 * FNW + warp] = n11;
        red_[1 * FNW + warp] = n12;
        red_[2 * FNW + warp] = n22;
    }
    __syncthreads();
    if (tid == 0) {
        float a11 = 0.f, a12 = 0.f, a22 = 0.f;
        for (int w = 0; w < FNW; w++) {
            a11 += red_[0 * FNW + w];
            a12 += red_[1 * FNW + w];
            a22 += red_[2 * FNW + w];
        }
        out[a * B2N + b] = a12 / ((sqrtf(a11) + EPSV) * (sqrtf(a22) + EPSV));
    }
}

// ---------------------------------------------------------------------------
extern "C" void kernel_launch(void* const* d_in, const int* in_sizes, int n_in,
                              void* d_out, int out_size) {
    const float* v1 = (const float*)d_in[0];
    const float* v2 = (const float*)d_in[1];
    const float* w_img = (const float*)d_in[2];
    const float* w_txt = (const float*)d_in[3];
    const float* w1a = (const float*)d_in[4];
    const float* b1a = (const float*)d_in[5];
    const float* w2a = (const float*)d_in[6];
    // d_in[7] = b2a (cancels exactly in softmax over N)
    const float* w1b = (const float*)d_in[8];
    const float* b1b = (const float*)d_in[9];
    const float* w2b = (const float*)d_in[10];
    // d_in[11] = b2b (cancels)
    float* out = (float*)d_out;

    static float* p_k1 = 0;
    static float* p_k2 = 0;
    static float* p_Za = 0;
    static float* p_Zb = 0;
    static float* p_C = 0;
    if (!p_k1) {
        cudaGetSymbolAddress((void**)&p_k1, g_k1);
        cudaGetSymbolAddress((void**)&p_k2, g_k2);
        cudaGetSymbolAddress((void**)&p_Za, g_Za);
        cudaGetSymbolAddress((void**)&p_Zb, g_Zb);
        cudaGetSymbolAddress((void**)&p_C, g_C);
    }

    const int M1 = B1N * RN;  // 1728
    const int M2 = B2N * LN;  // 1440

    dim3 gp(DN / GBN, (M1 + GBM - 1) / GBM, 4);
    gemm_proj<<<gp, 128>>>(v1, v2, w_img, w_txt, w1a, w1b, p_k1, p_k2, p_Za,
                           p_Zb);

    dim3 gc((M2 + GBN - 1) / GBN, M1 / GBM);
    gemm_cmat<<<gc, 128>>>(p_k1, p_k2, p_C);

    dim3 gf(B2N, B1N);
    fused_pair<<<gf, FTH>>>(v1, v2, p_C, p_Za, p_Zb, w2a, b1a, w2b, b1b, out);
}

// round 16
// speedup vs baseline: 1.0611x; 1.0611x over previous
#include <cuda_runtime.h>
#include <math.h>

#define B1N 48
#define B2N 48
#define RN 36
#define LN 30
#define DN 1024
#define HN 4
#define ECH 64
#define NCHUNK (DN / ECH)
#define ISD 0.03125f
#define EPSV 1e-8f

// Scratch (device globals; no allocation in kernel_launch)
__device__ float g_k1[B1N * RN * DN];            // 1728 x 1024
__device__ float g_k2[B2N * LN * DN];            // 1440 x 1024
__device__ float g_Za[B2N * LN * DN];            // 1440 x 1024  (v2 @ w1a^T)
__device__ float g_Zb[B1N * RN * DN];            // 1728 x 1024  (v1 @ w1b^T)
__device__ float g_C[(B1N * RN) * (B2N * LN)];   // 1728 x 1440  (k1 . k2)

// ---------------------------------------------------------------------------
// f32x2 packed FMA + cp.async helpers
// ---------------------------------------------------------------------------
typedef unsigned long long u64;

__device__ __forceinline__ u64 fma2(u64 a, u64 b, u64 c) {
    u64 d;
    asm("fma.rn.f32x2 %0, %1, %2, %3;" : "=l"(d) : "l"(a), "l"(b), "l"(c));
    return d;
}
__device__ __forceinline__ u64 dup2(float p) {
    u64 d;
    asm("mov.b64 %0, {%1, %1};" : "=l"(d) : "f"(p));
    return d;
}
__device__ __forceinline__ float2 unpack2(u64 v) {
    return *reinterpret_cast<float2*>(&v);
}

__device__ __forceinline__ unsigned s2u(const void* p) {
    return (unsigned)__cvta_generic_to_shared(p);
}
__device__ __forceinline__ void cp16(unsigned dst, const float* src) {
    asm volatile("cp.async.cg.shared.global [%0], [%1], 16;" ::"r"(dst),
                 "l"(src));
}
__device__ __forceinline__ void cp16z(unsigned dst, const float* src, int ok) {
    int sz = ok ? 16 : 0;
    asm volatile("cp.async.cg.shared.global [%0], [%1], 16, %2;" ::"r"(dst),
                 "l"(src), "r"(sz));
}
__device__ __forceinline__ void cp_commit() {
    asm volatile("cp.async.commit_group;");
}
__device__ __forceinline__ void cp_wait1() {
    asm volatile("cp.async.wait_group 1;");
}
__device__ __forceinline__ void cp_wait0() {
    asm volatile("cp.async.wait_group 0;");
}

// ---------------------------------------------------------------------------
// NT GEMM core (R11 config — measured best): BM=96, BN=64, 128 thr,
// 6x8 f32x2 microtile, GBK=32, rows padded to 36 floats.
// ---------------------------------------------------------------------------
#define GBM 96
#define GBN 64
#define GBK 32
#define GNT (DN / GBK)

template <bool GUARD>
__device__ __forceinline__ void gemm_core(const float* __restrict__ A,
                                          const float* __restrict__ B,
                                          float* __restrict__ C, int N, int m0,
                                          int n0) {
    __shared__ __align__(16) float As[2][GBM][36];
    __shared__ __align__(16) float Bs[2][GBN][36];

    const int tid = threadIdx.x;
    const int tx = tid & 7;
    const int ty = tid >> 3;

    u64 acc[6][8];
#pragma unroll
    for (int i = 0; i < 6; i++)
#pragma unroll
        for (int j = 0; j < 8; j++) acc[i][j] = 0ull;

    {
#pragma unroll
        for (int i = 0; i < 6; i++) {
            int idx = tid + i * 128;
            int r = idx >> 3, kq = idx & 7;
            cp16(s2u(&As[0][r][kq * 4]), A + (size_t)(m0 + r) * DN + kq * 4);
        }
#pragma unroll
        for (int i = 0; i < 4; i++) {
            int idx = tid + i * 128;
            int r = idx >> 3, kq = idx & 7;
            const float* src = B + (size_t)(n0 + r) * DN + kq * 4;
            if (GUARD)
                cp16z(s2u(&Bs[0][r][kq * 4]), src, n0 + r < N);
            else
                cp16(s2u(&Bs[0][r][kq * 4]), src);
        }
        cp_commit();
    }

    for (int kt = 0; kt < GNT; kt++) {
        const int buf = kt & 1;
        if (kt + 1 < GNT) {
            const int k0 = (kt + 1) * GBK;
            const int nb = buf ^ 1;
#pragma unroll
            for (int i = 0; i < 6; i++) {
                int idx = tid + i * 128;
                int r = idx >> 3, kq = idx & 7;
                cp16(s2u(&As[nb][r][kq * 4]),
                     A + (size_t)(m0 + r) * DN + k0 + kq * 4);
            }
#pragma unroll
            for (int i = 0; i < 4; i++) {
                int idx = tid + i * 128;
                int r = idx >> 3, kq = idx & 7;
                const float* src = B + (size_t)(n0 + r) * DN + k0 + kq * 4;
                if (GUARD)
                    cp16z(s2u(&Bs[nb][r][kq * 4]), src, n0 + r < N);
                else
                    cp16(s2u(&Bs[nb][r][kq * 4]), src);
            }
            cp_commit();
            cp_wait1();
        } else {
            cp_wait0();
        }
        __syncthreads();

#pragma unroll
        for (int p = 0; p < 16; p++) {
            u64 av[6], bv[8];
#pragma unroll
            for (int i = 0; i < 6; i++)
                av[i] = *reinterpret_cast<const u64*>(&As[buf][ty * 6 + i][2 * p]);
#pragma unroll
            for (int j = 0; j < 8; j++)
                bv[j] = *reinterpret_cast<const u64*>(&Bs[buf][j * 8 + tx][2 * p]);
#pragma unroll
            for (int i = 0; i < 6; i++)
#pragma unroll
                for (int j = 0; j < 8; j++)
                    acc[i][j] = fma2(av[i], bv[j], acc[i][j]);
        }
        __syncthreads();
    }

#pragma unroll
    for (int i = 0; i < 6; i++) {
        const int m = m0 + ty * 6 + i;
#pragma unroll
        for (int j = 0; j < 8; j++) {
            const int n = n0 + tx + j * 8;
            float2 v = *reinterpret_cast<float2*>(&acc[i][j]);
            if (!GUARD || n < N) C[(size_t)m * N + n] = v.x + v.y;
        }
    }
}

__global__ __launch_bounds__(128, 3) void gemm_proj(
    const float* __restrict__ v1, const float* __restrict__ v2,
    const float* __restrict__ w_img, const float* __restrict__ w_txt,
    const float* __restrict__ w1a, const float* __restrict__ w1b,
    float* __restrict__ k1, float* __restrict__ k2, float* __restrict__ Za,
    float* __restrict__ Zb) {
    const float* A;
    const float* B;
    float* C;
    int M;
    switch (blockIdx.z) {
        case 0: A = v1; B = w_img; C = k1; M = B1N * RN; break;
        case 1: A = v1; B = w1b; C = Zb; M = B1N * RN; break;
        case 2: A = v2; B = w_txt; C = k2; M = B2N * LN; break;
        default: A = v2; B = w1a; C = Za; M = B2N * LN; break;
    }
    const int m0 = blockIdx.y * GBM;
    if (m0 >= M) return;
    gemm_core<false>(A, B, C, DN, m0, blockIdx.x * GBN);
}

__global__ __launch_bounds__(128, 3) void gemm_cmat(
    const float* __restrict__ k1, const float* __restrict__ k2,
    float* __restrict__ C) {
    gemm_core<true>(k1, k2, C, B2N * LN, blockIdx.y * GBM, blockIdx.x * GBN);
}

// ---------------------------------------------------------------------------
// Fused per-(a,b)-pair kernel — 192 threads, WARP-ALIGNED H1/H2 split.
//   H1: warps 0-2 (tid 0..95):   12 r-groups x 3 rows, 8 e-lanes
//   H2: warps 3-5 (tid 96..191): 12 l-groups (10 used) x 3 rows, 8 e-lanes
// No warp executes both bodies -> balanced critical path.
// ---------------------------------------------------------------------------
#define FTH 192
#define FNW (FTH / 32)
#define EQ4 (ECH / 4)

__global__ __launch_bounds__(FTH) void fused_pair(
    const float* __restrict__ v1, const float* __restrict__ v2,
    const float* __restrict__ Cbig, const float* __restrict__ Za,
    const float* __restrict__ Zb, const float* __restrict__ w2a,
    const float* __restrict__ b1a, const float* __restrict__ w2b,
    const float* __restrict__ b1b, float* __restrict__ out) {
    const int b = blockIdx.x;
    const int a = blockIdx.y;
    const int tid = threadIdx.x;
    const int lane = tid & 31;
    const int warp = tid >> 5;

    __shared__ __align__(16) float ZacS[2][LN * ECH];
    __shared__ __align__(16) float ZbcS[2][RN * ECH];
    __shared__ __align__(16) float w2acS[2][HN * ECH];
    __shared__ __align__(16) float w2bcS[2][HN * ECH];
    __shared__ __align__(16) float b1acS[2][ECH];
    __shared__ __align__(16) float b1bcS[2][ECH];
    __shared__ __align__(16) float p2s[RN][LN];   // softmax over l
    __shared__ __align__(16) float p1s[LN][RN];   // softmax over r
    __shared__ float sa[RN][HN];
    __shared__ float sb[LN][HN];

    float* Csp = ZbcS[1];
    float* pa_ = ZbcS[0];
    float* pb_ = pa_ + HN * RN;
    float* tr_ = pb_ + HN * LN;
    float* tl_ = tr_ + RN;
    float* qa_ = tl_ + LN;
    float* qb_ = qa_ + LN;
    float* red_ = qb_ + RN;

    const float* ZaB = Za + (size_t)b * LN * DN;
    const float* ZbA = Zb + (size_t)a * RN * DN;

    auto stage = [&](int c, int sb_) {
        const int e0c = c * ECH;
        for (int p = tid; p < LN * EQ4; p += FTH) {
            int l = p >> 4, q = p & 15;
            cp16(s2u(&ZacS[sb_][l * ECH + q * 4]),
                 ZaB + (size_t)l * DN + e0c + q * 4);
        }
        for (int p = tid; p < RN * EQ4; p += FTH) {
            int r = p >> 4, q = p & 15;
            cp16(s2u(&ZbcS[sb_][r * ECH + q * 4]),
                 ZbA + (size_t)r * DN + e0c + q * 4);
        }
        for (int p = tid; p < HN * EQ4; p += FTH) {
            int h = p >> 4, q = p & 15;
            cp16(s2u(&w2acS[sb_][h * ECH + q * 4]), w2a + h * DN + e0c + q * 4);
            cp16(s2u(&w2bcS[sb_][h * ECH + q * 4]), w2b + h * DN + e0c + q * 4);
        }
        if (tid < EQ4)
            cp16(s2u(&b1acS[sb_][tid * 4]), b1a + e0c + tid * 4);
        else if (tid < 2 * EQ4)
            cp16(s2u(&b1bcS[sb_][(tid - EQ4) * 4]), b1b + e0c + (tid - EQ4) * 4);
    };

    stage(0, 0);
    cp_commit();

    for (int p = tid; p < RN * LN; p += FTH) {
        int r = p / LN, l = p % LN;
        Csp[p] = Cbig[(size_t)(a * RN + r) * (B2N * LN) + b * LN + l] * ISD;
    }
    __syncthreads();

    for (int r = warp; r < RN; r += FNW) {
        float x = (lane < LN) ? Csp[r * LN + lane] : -1e30f;
        float m = x;
#pragma unroll
        for (int o = 16; o; o >>= 1) m = fmaxf(m, __shfl_xor_sync(~0u, m, o));
        float e = (lane < LN) ? __expf(x - m) : 0.f;
        float s = e;
#pragma unroll
        for (int o = 16; o; o >>= 1) s += __shfl_xor_sync(~0u, s, o);
        if (lane < LN) p2s[r][lane] = e / s;
    }
    for (int l = warp; l < LN; l += FNW) {
        float x0 = Csp[lane * LN + l];
        float x1 = (lane < RN - 32) ? Csp[(lane + 32) * LN + l] : -1e30f;
        float m = fmaxf(x0, x1);
#pragma unroll
        for (int o = 16; o; o >>= 1) m = fmaxf(m, __shfl_xor_sync(~0u, m, o));
        float e0 = __expf(x0 - m);
        float e1 = (lane < RN - 32) ? __expf(x1 - m) : 0.f;
        float s = e0 + e1;
#pragma unroll
        for (int o = 16; o; o >>= 1) s += __shfl_xor_sync(~0u, s, o);
        p1s[l][lane] = e0 / s;
        if (lane < RN - 32) p1s[l][lane + 32] = e1 / s;
    }
    __syncthreads();

    // warp-aligned roles
    const int isH1 = (tid < 96);
    const int grp = (isH1 ? tid : tid - 96) >> 3;   // 0..11
    const int el = tid & 7;
    const int r0 = grp * 3;                          // H1 rows
    const int l0 = grp * 3;                          // H2 rows
    const int h2on = (!isH1) && (grp < 10);
    const int eb = el * 4;

    float saacc[3][4];
    float sbacc[3][4];
#pragma unroll
    for (int i = 0; i < 3; i++)
#pragma unroll
        for (int h = 0; h < 4; h++) {
            saacc[i][h] = 0.f;
            sbacc[i][h] = 0.f;
        }

    for (int c = 0; c < NCHUNK; c++) {
        const int buf = c & 1;
        if (c + 1 < NCHUNK) {
            stage(c + 1, buf ^ 1);
            cp_commit();
            cp_wait1();
        } else {
            cp_wait0();
        }
        __syncthreads();

        if (isH1) {
            u64 tmp[3][4];
#pragma unroll
            for (int i = 0; i < 3; i++)
#pragma unroll
                for (int k = 0; k < 4; k++) tmp[i][k] = 0ull;
            for (int l = 0; l < LN; l += 2) {
                float4 za0 = *reinterpret_cast<const float4*>(
                    &ZacS[buf][l * ECH + eb]);
                float4 za1 = *reinterpret_cast<const float4*>(
                    &ZacS[buf][l * ECH + eb + 32]);
                float4 zb0 = *reinterpret_cast<const float4*>(
                    &ZacS[buf][(l + 1) * ECH + eb]);
                float4 zb1 = *reinterpret_cast<const float4*>(
                    &ZacS[buf][(l + 1) * ECH + eb + 32]);
                u64 zA[4], zB[4];
                zA[0] = *reinterpret_cast<u64*>(&za0.x);
                zA[1] = *reinterpret_cast<u64*>(&za0.z);
                zA[2] = *reinterpret_cast<u64*>(&za1.x);
                zA[3] = *reinterpret_cast<u64*>(&za1.z);
                zB[0] = *reinterpret_cast<u64*>(&zb0.x);
                zB[1] = *reinterpret_cast<u64*>(&zb0.z);
                zB[2] = *reinterpret_cast<u64*>(&zb1.x);
                zB[3] = *reinterpret_cast<u64*>(&zb1.z);
#pragma unroll
                for (int i = 0; i < 3; i++) {
                    u64 pp = *reinterpret_cast<const u64*>(&p2s[r0 + i][l]);
                    float2 pv = unpack2(pp);
                    u64 pd0 = dup2(pv.x);
                    u64 pd1 = dup2(pv.y);
#pragma unroll
                    for (int k = 0; k < 4; k++) {
                        tmp[i][k] = fma2(pd0, zA[k], tmp[i][k]);
                        tmp[i][k] = fma2(pd1, zB[k], tmp[i][k]);
                    }
                }
            }
#pragma unroll
            for (int k = 0; k < 4; k++) {
                const int e = eb + (k & 1) * 2 + (k >> 1) * 32;
                float bb0 = b1acS[buf][e], bb1 = b1acS[buf][e + 1];
                float w0[4], w1[4];
#pragma unroll
                for (int h = 0; h < 4; h++) {
                    w0[h] = w2acS[buf][h * ECH + e];
                    w1[h] = w2acS[buf][h * ECH + e + 1];
                }
#pragma unroll
                for (int i = 0; i < 3; i++) {
                    float2 t = unpack2(tmp[i][k]);
                    float h0 = fmaxf(t.x + bb0, 0.f);
                    float h1 = fmaxf(t.y + bb1, 0.f);
#pragma unroll
                    for (int h = 0; h < 4; h++)
                        saacc[i][h] += w0[h] * h0 + w1[h] * h1;
                }
            }
        } else if (h2on) {
            u64 tmp[3][4];
#pragma unroll
            for (int i = 0; i < 3; i++)
#pragma unroll
                for (int k = 0; k < 4; k++) tmp[i][k] = 0ull;
            for (int r = 0; r < RN; r += 2) {
                float4 za0 = *reinterpret_cast<const float4*>(
                    &ZbcS[buf][r * ECH + eb]);
                float4 za1 = *reinterpret_cast<const float4*>(
                    &ZbcS[buf][r * ECH + eb + 32]);
                float4 zb0 = *reinterpret_cast<const float4*>(
                    &ZbcS[buf][(r + 1) * ECH + eb]);
                float4 zb1 = *reinterpret_cast<const float4*>(
                    &ZbcS[buf][(r + 1) * ECH + eb + 32]);
                u64 zA[4], zB[4];
                zA[0] = *reinterpret_cast<u64*>(&za0.x);
                zA[1] = *reinterpret_cast<u64*>(&za0.z);
                zA[2] = *reinterpret_cast<u64*>(&za1.x);
                zA[3] = *reinterpret_cast<u64*>(&za1.z);
                zB[0] = *reinterpret_cast<u64*>(&zb0.x);
                zB[1] = *reinterpret_cast<u64*>(&zb0.z);
                zB[2] = *reinterpret_cast<u64*>(&zb1.x);
                zB[3] = *reinterpret_cast<u64*>(&zb1.z);
#pragma unroll
                for (int i = 0; i < 3; i++) {
                    u64 pp = *reinterpret_cast<const u64*>(&p1s[l0 + i][r]);
                    float2 pv = unpack2(pp);
                    u64 pd0 = dup2(pv.x);
                    u64 pd1 = dup2(pv.y);
#pragma unroll
                    for (int k = 0; k < 4; k++) {
                        tmp[i][k] = fma2(pd0, zA[k], tmp[i][k]);
                        tmp[i][k] = fma2(pd1, zB[k], tmp[i][k]);
                    }
                }
            }
#pragma unroll
            for (int k = 0; k < 4; k++) {
                const int e = eb + (k & 1) * 2 + (k >> 1) * 32;
                float bb0 = b1bcS[buf][e], bb1 = b1bcS[buf][e + 1];
                float w0[4], w1[4];
#pragma unroll
                for (int h = 0; h < 4; h++) {
                    w0[h] = w2bcS[buf][h * ECH + e];
                    w1[h] = w2bcS[buf][h * ECH + e + 1];
                }
#pragma unroll
                for (int i = 0; i < 3; i++) {
                    float2 t = unpack2(tmp[i][k]);
                    float h0 = fmaxf(t.x + bb0, 0.f);
                    float h1 = fmaxf(t.y + bb1, 0.f);
#pragma unroll
                    for (int h = 0; h < 4; h++)
                        sbacc[i][h] += w0[h] * h0 + w1[h] * h1;
                }
            }
        }
        __syncthreads();
    }

    // ---- Phase 2 writeback: reduce across the 8 e-lanes of each group ----
    {
        const unsigned gm = 0xFFu << (lane & 24);
        if (isH1) {
#pragma unroll
            for (int off = 4; off; off >>= 1)
#pragma unroll
                for (int i = 0; i < 3; i++)
#pragma unroll
                    for (int h = 0; h < 4; h++)
                        saacc[i][h] += __shfl_xor_sync(gm, saacc[i][h], off);
            if (el == 0)
#pragma unroll
                for (int i = 0; i < 3; i++)
#pragma unroll
                    for (int h = 0; h < 4; h++) sa[r0 + i][h] = saacc[i][h];
        } else if (h2on) {
#pragma unroll
            for (int off = 4; off; off >>= 1)
#pragma unroll
                for (int i = 0; i < 3; i++)
#pragma unroll
                    for (int h = 0; h < 4; h++)
                        sbacc[i][h] += __shfl_xor_sync(gm, sbacc[i][h], off);
            if (el == 0)
#pragma unroll
                for (int i = 0; i < 3; i++)
#pragma unroll
                    for (int h = 0; h < 4; h++) sb[l0 + i][h] = sbacc[i][h];
        }
    }
    __syncthreads();

    // ---- Phase 3: head softmaxes ----
    if (tid < HN) {
        int h = tid;
        float m = -1e30f;
        for (int r = 0; r < RN; r++) m = fmaxf(m, sa[r][h]);
        float s = 0.f;
        for (int r = 0; r < RN; r++) {
            float e = __expf(sa[r][h] - m);
            pa_[h * RN + r] = e;
            s += e;
        }
        float inv = 1.f / s;
        for (int r = 0; r < RN; r++) pa_[h * RN + r] *= inv;
    } else if (tid < 2 * HN) {
        int h = tid - HN;
        float m = -1e30f;
        for (int l = 0; l < LN; l++) m = fmaxf(m, sb[l][h]);
        float s = 0.f;
        for (int l = 0; l < LN; l++) {
            float e = __expf(sb[l][h] - m);
            pb_[h * LN + l] = e;
            s += e;
        }
        float inv = 1.f / s;
        for (int l = 0; l < LN; l++) pb_[h * LN + l] *= inv;
    }
    __syncthreads();

    // ---- Phase 4: collapse to qbar coefficients ----
    if (tid < RN) {
        float s = 0.f;
        for (int h = 0; h < HN; h++) s += pa_[h * RN + tid];
        tr_[tid] = s;
    } else if (tid >= 64 && tid < 64 + LN) {
        int l = tid - 64;
        float s = 0.f;
        for (int h = 0; h < HN; h++) s += pb_[h * LN + l];
        tl_[l] = s;
    }
    __syncthreads();
    if (tid < LN) {
        float s = 0.f;
        for (int r = 0; r < RN; r++) s += tr_[r] * p2s[r][tid];
        qa_[tid] = 0.25f * s;
    } else if (tid >= 64 && tid < 64 + RN) {
        int r = tid - 64;
        float s = 0.f;
        for (int l = 0; l < LN; l++) s += tl_[l] * p1s[l][r];
        qb_[r] = 0.25f * s;
    }
    __syncthreads();

    // ---- Phase 5: stream d, accumulate cosine terms ----
    float n11 = 0.f, n12 = 0.f, n22 = 0.f;
    const float* v2b = v2 + (size_t)b * LN * DN;
    const float* v1a = v1 + (size_t)a * RN * DN;
    for (int d = tid; d < DN; d += FTH) {
        float u1 = 0.f;
#pragma unroll
        for (int l = 0; l < LN; l++) u1 += qa_[l] * v2b[(size_t)l * DN + d];
        float u2 = 0.f;
#pragma unroll
        for (int r = 0; r < RN; r++) u2 += qb_[r] * v1a[(size_t)r * DN + d];
        n11 += u1 * u1;
        n12 += u1 * u2;
        n22 += u2 * u2;
    }
#pragma unroll
    for (int o = 16; o; o >>= 1) {
        n11 += __shfl_xor_sync(~0u, n11, o);
        n12 += __shfl_xor_sync(~0u, n12, o);
        n22 += __shfl_xor_sync(~0u, n22, o);
    }
    if (lane == 0) {
        red_[0 * FNW + warp] = n11;
        red_[1 * FNW + warp] = n12;
        red_[2 * FNW + warp] = n22;
    }
    __syncthreads();
    if (tid == 0) {
        float a11 = 0.f, a12 = 0.f, a22 = 0.f;
        for (int w = 0; w < FNW; w++) {
            a11 += red_[0 * FNW + w];
            a12 += red_[1 * FNW + w];
            a22 += red_[2 * FNW + w];
        }
        out[a * B2N + b] = a12 / ((sqrtf(a11) + EPSV) * (sqrtf(a22) + EPSV));
    }
}

// ---------------------------------------------------------------------------
extern "C" void kernel_launch(void* const* d_in, const int* in_sizes, int n_in,
                              void* d_out, int out_size) {
    const float* v1 = (const float*)d_in[0];
    const float* v2 = (const float*)d_in[1];
    const float* w_img = (const float*)d_in[2];
    const float* w_txt = (const float*)d_in[3];
    const float* w1a = (const float*)d_in[4];
    const float* b1a = (const float*)d_in[5];
    const float* w2a = (const float*)d_in[6];
    // d_in[7] = b2a (cancels exactly in softmax over N)
    const float* w1b = (const float*)d_in[8];
    const float* b1b = (const float*)d_in[9];
    const float* w2b = (const float*)d_in[10];
    // d_in[11] = b2b (cancels)
    float* out = (float*)d_out;

    static float* p_k1 = 0;
    static float* p_k2 = 0;
    static float* p_Za = 0;
    static float* p_Zb = 0;
    static float* p_C = 0;
    if (!p_k1) {
        cudaGetSymbolAddress((void**)&p_k1, g_k1);
        cudaGetSymbolAddress((void**)&p_k2, g_k2);
        cudaGetSymbolAddress((void**)&p_Za, g_Za);
        cudaGetSymbolAddress((void**)&p_Zb, g_Zb);
        cudaGetSymbolAddress((void**)&p_C, g_C);
    }

    const int M1 = B1N * RN;  // 1728
    const int M2 = B2N * LN;  // 1440

    dim3 gp(DN / GBN, (M1 + GBM - 1) / GBM, 4);
    gemm_proj<<<gp, 128>>>(v1, v2, w_img, w_txt, w1a, w1b, p_k1, p_k2, p_Za,
                           p_Zb);

    dim3 gc((M2 + GBN - 1) / GBN, M1 / GBM);
    gemm_cmat<<<gc, 128>>>(p_k1, p_k2, p_C);

    dim3 gf(B2N, B1N);
    fused_pair<<<gf, FTH>>>(v1, v2, p_C, p_Za, p_Zb, w2a, b1a, w2b, b1b, out);
}